// round 6
// baseline (speedup 1.0000x reference)
#include <cuda_runtime.h>
#include <cstdint>

#define NF    16
#define NP    120
#define EMB   256
#define BATCH 2048

// ---- tcgen05 feature gate: only valid when the compile pass targets sm_103a/f ----
#if defined(__CUDA_ARCH__)
#  if (__CUDA_ARCH__ == 1030) && (defined(__CUDA_ARCH_FEAT_SM103_ALL) || \
       defined(__CUDA_ARCH_SPECIFIC__) || defined(__CUDA_ARCH_FAMILY_SPECIFIC__))
#    define USE_TCGEN 1
#  else
#    define USE_TCGEN 0
#  endif
#else
#  define USE_TCGEN 0
#endif

// ---- shared constants ----
#define BM 128
#define BN 256                    // full EMB per CTA
#define BK 32
#define NSTAGE 2
#define NITER  (EMB / BK)                 // 8 k-slabs
#define A_BYTES (BM * BK * 4)             // 16384
#define B_BYTES (BN * BK * 4)             // 32768
#define STAGE_BYTES (A_BYTES + B_BYTES)   // 49152
#define MBAR_OFF 16
#define STAGE0_OFF 1024
#define SMEM_NEEDED (STAGE0_OFF + NSTAGE * STAGE_BYTES)   // 99328
#define SMEM_ALLOC  (SMEM_NEEDED + 1024)                  // 100352 -> 2 CTAs/SM

#define TMEM_COLS 256
// idesc: dtype=F32(1)<<4, atype=TF32(2)<<7, btype=TF32(2)<<10, N/8<<17, M/16<<24
#define IDESC ((1u << 4) | (2u << 7) | (2u << 10) | ((BN / 8) << 17) | ((BM / 16) << 24))

__device__ float g_Wt[(size_t)NP * EMB * EMB];   // W^T scratch, [p][n][k], tf32-rounded

__device__ __forceinline__ float round_tf32(float v) {
    uint32_t u;
    asm("cvt.rna.tf32.f32 %0, %1;" : "=r"(u) : "f"(v));
    return __uint_as_float(u);
}

// ---------------- transpose W[p][k][n] -> g_Wt[p][n][k] ----------------
__global__ void transpose_w(const float* __restrict__ W) {
    __shared__ float t[32][33];
    const int p  = blockIdx.z;
    const int kb = blockIdx.x * 32;
    const int nb = blockIdx.y * 32;
    const float* Wp = W + (size_t)p * EMB * EMB;
    float* Wtp = g_Wt + (size_t)p * EMB * EMB;
    const int tx = threadIdx.x;
#pragma unroll
    for (int i = threadIdx.y; i < 32; i += 8)
        t[i][tx] = round_tf32(Wp[(size_t)(kb + i) * EMB + nb + tx]);
    __syncthreads();
#pragma unroll
    for (int i = threadIdx.y; i < 32; i += 8)
        Wtp[(size_t)(nb + i) * EMB + kb + tx] = t[tx][i];
}

#if USE_TCGEN
// ---------------- tcgen05 helpers ----------------
__device__ __forceinline__ uint32_t smem_u32(const void* p) {
    uint32_t a;
    asm("{ .reg .u64 t; cvta.to.shared.u64 t, %1; cvt.u32.u64 %0, t; }" : "=r"(a) : "l"(p));
    return a;
}
__device__ __forceinline__ uint32_t elect_one() {
    uint32_t pred;
    asm volatile("{ .reg .pred p; elect.sync _|p, 0xFFFFFFFF; selp.b32 %0, 1, 0, p; }" : "=r"(pred));
    return pred;
}
static __device__ __forceinline__ uint64_t make_desc(uint32_t addr) {
    // SW128 K-major: layout=2, version=1, SBO=64 (1024B), LBO=1 (16B)
    return ((uint64_t)2 << 61) | ((uint64_t)1 << 46) | ((uint64_t)64 << 32) |
           ((uint64_t)1 << 16) | (((uint64_t)addr >> 4) & 0x3FFF);
}
#define MBAR_INIT(a, n) asm volatile("mbarrier.init.shared.b64 [%0], %1;" :: "r"(a), "r"(n) : "memory")
__device__ __forceinline__ void mbar_wait(uint32_t mbar, uint32_t parity) {
    uint32_t done;
    asm volatile(
        "{ .reg .pred p; mbarrier.try_wait.parity.acquire.cta.shared::cta.b64 p, [%1], %2; selp.b32 %0, 1, 0, p; }"
        : "=r"(done) : "r"(mbar), "r"(parity) : "memory");
    if (!done) {
        asm volatile(
            "{ .reg .pred P1;\n"
            "W_%=: mbarrier.try_wait.parity.acquire.cta.shared::cta.b64 P1, [%0], %1, 0x989680;\n"
            "@P1 bra.uni D_%=; bra.uni W_%=;\nD_%=: }"
            :: "r"(mbar), "r"(parity) : "memory");
    }
}
__device__ __forceinline__ void cp16(uint32_t dst, const void* src) {
    asm volatile("cp.async.cg.shared.global [%0], [%1], 16;" :: "r"(dst), "l"(src));
}
#define CP_COMMIT() asm volatile("cp.async.commit_group;" ::: "memory")
#define CP_WAIT1()  asm volatile("cp.async.wait_group 1;" ::: "memory")
__device__ __forceinline__ void mma_tf32_ss(uint32_t d, uint64_t a, uint64_t b,
                                            uint32_t idesc, uint32_t en) {
    asm volatile(
        "{ .reg .pred p; setp.ne.u32 p, %4, 0;\n"
        "tcgen05.mma.cta_group::1.kind::tf32 [%0], %1, %2, %3, {%5,%5,%5,%5}, p; }"
        :: "r"(d), "l"(a), "l"(b), "r"(idesc), "r"(en), "r"(0u) : "memory");
}
#define TC_COMMIT(mbar) \
    asm volatile("tcgen05.commit.cta_group::1.mbarrier::arrive::one.shared::cluster.b64 [%0];" \
                 :: "r"(mbar) : "memory")
#define FENCE_ASYNC()     asm volatile("fence.proxy.async.shared::cta;" ::: "memory")
#define TC_FENCE_AFTER()  asm volatile("tcgen05.fence::after_thread_sync;" ::: "memory")
#define TC_FENCE_BEFORE() asm volatile("tcgen05.fence::before_thread_sync;" ::: "memory")
#define LDTM_X32(r, addr) \
    asm volatile("tcgen05.ld.sync.aligned.32x32b.x32.b32 " \
        "{%0,%1,%2,%3,%4,%5,%6,%7,%8,%9,%10,%11,%12,%13,%14,%15," \
        "%16,%17,%18,%19,%20,%21,%22,%23,%24,%25,%26,%27,%28,%29,%30,%31}, [%32];" \
        : "=r"((r)[0]),"=r"((r)[1]),"=r"((r)[2]),"=r"((r)[3]),"=r"((r)[4]),"=r"((r)[5]),"=r"((r)[6]),"=r"((r)[7]), \
          "=r"((r)[8]),"=r"((r)[9]),"=r"((r)[10]),"=r"((r)[11]),"=r"((r)[12]),"=r"((r)[13]),"=r"((r)[14]),"=r"((r)[15]), \
          "=r"((r)[16]),"=r"((r)[17]),"=r"((r)[18]),"=r"((r)[19]),"=r"((r)[20]),"=r"((r)[21]),"=r"((r)[22]),"=r"((r)[23]), \
          "=r"((r)[24]),"=r"((r)[25]),"=r"((r)[26]),"=r"((r)[27]),"=r"((r)[28]),"=r"((r)[29]),"=r"((r)[30]),"=r"((r)[31]) \
        : "r"(addr))
#define TC_WAIT_LD() asm volatile("tcgen05.wait::ld.sync.aligned;" ::: "memory")

__device__ __forceinline__ uint32_t swz(uint32_t off) { return off ^ ((off >> 3) & 0x70); }
#endif  // USE_TCGEN

#if !USE_TCGEN
// legacy mma.sync helpers (fallback cubin; not selected on GB300)
__device__ __forceinline__ uint32_t f2tf32(float v) {
    uint32_t u;
    asm("cvt.rna.tf32.f32 %0, %1;" : "=r"(u) : "f"(v));
    return u;
}
__device__ __forceinline__ void mma_tf32_16x8x8(float* d, const uint32_t* a, const uint32_t* b) {
    asm volatile(
        "mma.sync.aligned.m16n8k8.row.col.f32.tf32.tf32.f32 "
        "{%0,%1,%2,%3}, {%4,%5,%6,%7}, {%8,%9}, {%0,%1,%2,%3};"
        : "+f"(d[0]), "+f"(d[1]), "+f"(d[2]), "+f"(d[3])
        : "r"(a[0]), "r"(a[1]), "r"(a[2]), "r"(a[3]), "r"(b[0]), "r"(b[1]));
}
#endif

// ================= fused bilinear kernel: one symbol, two arch paths =================
// grid(16, 120), block 256, dynamic smem SMEM_ALLOC
__global__ __launch_bounds__(256, 2)
void bilinear_fused(const float* __restrict__ emb,
                    const float* __restrict__ weight,
                    const float* __restrict__ bias,
                    float* __restrict__ out) {
    const int tid = threadIdx.x;
    const int p   = blockIdx.y;
    // pair p -> (r_idx, c_idx) of triu_indices(16, 1)
    int r_idx = 0, rem = p;
    while (rem >= NF - 1 - r_idx) { rem -= NF - 1 - r_idx; r_idx++; }
    const int c_idx = r_idx + 1 + rem;
    const int m0 = blockIdx.x * BM;

#if USE_TCGEN
    // -------------------------------------------------- tcgen05 tf32 SS pipeline
    extern __shared__ char smem_raw[];
    const uint32_t base = (smem_u32(smem_raw) + 1023u) & ~1023u;
    const int wid  = tid >> 5;
    const int lane = tid & 31;

    if (wid == 0) {
        asm volatile("tcgen05.alloc.cta_group::1.sync.aligned.shared::cta.b32 [%0], %1;"
                     :: "r"(base), "r"((uint32_t)TMEM_COLS) : "memory");
    }
    if (tid == 0) {
#pragma unroll
        for (int s = 0; s < NSTAGE; s++) MBAR_INIT(base + MBAR_OFF + s * 8, 1);
    }
    __syncthreads();
    uint32_t tmem;
    asm volatile("ld.shared.b32 %0, [%1];" : "=r"(tmem) : "r"(base));

    const float* Wtp = g_Wt + (size_t)p * EMB * EMB;

    auto load_stage = [&](int s, int k0) {
        const uint32_t st = base + STAGE0_OFF + s * STAGE_BYTES;
#pragma unroll
        for (int i = 0; i < 4; i++) {                    // A: 128 rows x 8 chunks
            int idx = tid + i * 256;
            int m = idx >> 3, c = idx & 7;
            cp16(st + swz((m << 7) | (c << 4)),
                 emb + ((size_t)(m0 + m) * NF + r_idx) * EMB + k0 + c * 4);
        }
#pragma unroll
        for (int i = 0; i < 8; i++) {                    // B: 256 n-rows x 8 chunks
            int idx = tid + i * 256;
            int n = idx >> 3, c = idx & 7;
            cp16(st + A_BYTES + swz((n << 7) | (c << 4)),
                 Wtp + (size_t)n * EMB + k0 + c * 4);
        }
    };

    // prologue: stage 0
    load_stage(0, 0);
    CP_COMMIT();

    for (int it = 0; it < NITER; it++) {
        const int s = it & (NSTAGE - 1);
        const int j = it + 1;                      // next stage to load
        if (j < NITER) {
            const int s2 = j & (NSTAGE - 1);
            if (j >= NSTAGE)                       // slot reuse: wait prior occupant's MMA
                mbar_wait(base + MBAR_OFF + s2 * 8, ((j - NSTAGE) >> 1) & 1);
            load_stage(s2, j * BK);
        }
        CP_COMMIT();                               // uniform group count
        CP_WAIT1();                                // stage `it` resident
        FENCE_ASYNC();
        __syncthreads();

        if (wid == 0 && elect_one()) {
            const uint32_t st = base + STAGE0_OFF + s * STAGE_BYTES;
            const uint64_t ad = make_desc(st);
            const uint64_t bd = make_desc(st + A_BYTES);
#pragma unroll
            for (int jj = 0; jj < 4; jj++)         // 4 x (K=8) per 32-float slab
                mma_tf32_ss(tmem, ad + jj * 2, bd + jj * 2, IDESC,
                            (it == 0 && jj == 0) ? 0u : 1u);
            TC_COMMIT(base + MBAR_OFF + s * 8);
        }
    }

    // final MMA completion: slot (NITER-1)&1 = 1; 4th arrival -> phase 3 -> parity 1
    mbar_wait(base + MBAR_OFF + ((NITER - 1) & (NSTAGE - 1)) * 8, 1);
    TC_FENCE_AFTER();

    // epilogue: warps 0-3 -> cols [0,128), warps 4-7 -> cols [128,256)
    // row = (wid&3)*32 + lane (warp reads its own TMEM subpartition)
    {
        const int sub  = wid & 3;
        const int half = wid >> 2;
        const int m = m0 + sub * 32 + lane;
        const float* qrow = emb + ((size_t)m * NF + c_idx) * EMB;
        const float* brow = bias + (size_t)p * EMB;
        float* orow = out + ((size_t)m * NP + p) * EMB;
#pragma unroll
        for (int c = 0; c < 4; c++) {
            const int col = half * 128 + c * 32;
            uint32_t r[32];
            LDTM_X32(r, tmem + col);
            TC_WAIT_LD();
#pragma unroll
            for (int jj = 0; jj < 8; jj++) {
                const int gn = col + jj * 4;
                const float4 q  = *(const float4*)(qrow + gn);
                const float4 bb = *(const float4*)(brow + gn);
                float4 o;
                o.x = __uint_as_float(r[jj * 4 + 0]) * q.x + bb.x;
                o.y = __uint_as_float(r[jj * 4 + 1]) * q.y + bb.y;
                o.z = __uint_as_float(r[jj * 4 + 2]) * q.z + bb.z;
                o.w = __uint_as_float(r[jj * 4 + 3]) * q.w + bb.w;
                *(float4*)(orow + gn) = o;
            }
        }
    }
    TC_FENCE_BEFORE();
    __syncthreads();
    if (wid == 0) {
        asm volatile("tcgen05.relinquish_alloc_permit.cta_group::1.sync.aligned;");
        asm volatile("tcgen05.dealloc.cta_group::1.sync.aligned.b32 %0, %1;"
                     :: "r"(tmem), "r"((uint32_t)TMEM_COLS));
    }

#else
    // -------------------------------------------------- legacy mma.sync tf32 fallback
    // covers the 128x256 CTA tile as two 128x128 passes
    __shared__ uint32_t As[BK * 132];
    __shared__ uint32_t Bs[BK * 132];
    const int lane = tid & 31;
    const int warp = tid >> 5;
    const int warp_m = warp & 3;
    const int warp_n = warp >> 2;
    const float* Wp = weight + (size_t)p * EMB * EMB;
    const int lr = lane >> 2;
    const int lc = lane & 3;

    for (int nb = 0; nb < 2; nb++) {
        const int n0 = nb * 128;
        float acc[2][8][4];
#pragma unroll
        for (int i = 0; i < 2; i++)
#pragma unroll
            for (int j = 0; j < 8; j++)
#pragma unroll
                for (int r = 0; r < 4; r++) acc[i][j][r] = 0.0f;

        for (int k0 = 0; k0 < EMB; k0 += BK) {
            __syncthreads();
#pragma unroll
            for (int it = 0; it < 4; it++) {
                int fid = tid + it * 256;
                int m   = fid >> 3;
                int k4  = fid & 7;
                const float4 v = *(const float4*)(emb + ((size_t)(m0 + m) * NF + r_idx) * EMB + k0 + k4 * 4);
                As[(k4 * 4 + 0) * 132 + m] = f2tf32(v.x);
                As[(k4 * 4 + 1) * 132 + m] = f2tf32(v.y);
                As[(k4 * 4 + 2) * 132 + m] = f2tf32(v.z);
                As[(k4 * 4 + 3) * 132 + m] = f2tf32(v.w);
            }
#pragma unroll
            for (int it = 0; it < 4; it++) {
                int fid = tid + it * 256;
                int k   = fid >> 5;
                int n4  = fid & 31;
                const float4 w = *(const float4*)(Wp + (size_t)(k0 + k) * EMB + n0 + n4 * 4);
                Bs[k * 132 + n4 * 4 + 0] = f2tf32(w.x);
                Bs[k * 132 + n4 * 4 + 1] = f2tf32(w.y);
                Bs[k * 132 + n4 * 4 + 2] = f2tf32(w.z);
                Bs[k * 132 + n4 * 4 + 3] = f2tf32(w.w);
            }
            __syncthreads();

#pragma unroll
            for (int kk = 0; kk < BK; kk += 8) {
                uint32_t a[2][4];
                uint32_t b[8][2];
#pragma unroll
                for (int i = 0; i < 2; i++) {
                    int mbase = warp_m * 32 + i * 16 + lr;
                    a[i][0] = As[(kk + lc) * 132 + mbase];
                    a[i][1] = As[(kk + lc) * 132 + mbase + 8];
                    a[i][2] = As[(kk + lc + 4) * 132 + mbase];
                    a[i][3] = As[(kk + lc + 4) * 132 + mbase + 8];
                }
#pragma unroll
                for (int j = 0; j < 8; j++) {
                    int nbase = warp_n * 64 + j * 8 + lr;
                    b[j][0] = Bs[(kk + lc) * 132 + nbase];
                    b[j][1] = Bs[(kk + lc + 4) * 132 + nbase];
                }
#pragma unroll
                for (int i = 0; i < 2; i++)
#pragma unroll
                    for (int j = 0; j < 8; j++)
                        mma_tf32_16x8x8(acc[i][j], a[i], b[j]);
            }
        }

#pragma unroll
        for (int i = 0; i < 2; i++) {
            const int gm0 = m0 + warp_m * 32 + i * 16 + lr;
#pragma unroll
            for (int j = 0; j < 8; j++) {
                const int gn = n0 + warp_n * 64 + j * 8 + lc * 2;
                const float2 bs = *(const float2*)(bias + (size_t)p * EMB + gn);

                const float2 q0 = *(const float2*)(emb + ((size_t)gm0 * NF + c_idx) * EMB + gn);
                float2 o0;
                o0.x = acc[i][j][0] * q0.x + bs.x;
                o0.y = acc[i][j][1] * q0.y + bs.y;
                *(float2*)(out + ((size_t)gm0 * NP + p) * EMB + gn) = o0;

                const float2 q1 = *(const float2*)(emb + ((size_t)(gm0 + 8) * NF + c_idx) * EMB + gn);
                float2 o1;
                o1.x = acc[i][j][2] * q1.x + bs.x;
                o1.y = acc[i][j][3] * q1.y + bs.y;
                *(float2*)(out + ((size_t)(gm0 + 8) * NP + p) * EMB + gn) = o1;
            }
        }
        __syncthreads();
    }
#endif
}

extern "C" void kernel_launch(void* const* d_in, const int* in_sizes, int n_in,
                              void* d_out, int out_size) {
    const float* emb    = (const float*)d_in[0];
    const float* weight = (const float*)d_in[1];
    const float* bias   = (const float*)d_in[2];
    float* out          = (float*)d_out;

    cudaFuncSetAttribute(bilinear_fused, cudaFuncAttributeMaxDynamicSharedMemorySize, SMEM_ALLOC);

    transpose_w<<<dim3(8, 8, NP), dim3(32, 8)>>>(weight);
    bilinear_fused<<<dim3(BATCH / BM, NP), 256, SMEM_ALLOC>>>(emb, weight, bias, out);
}

// round 7
// speedup vs baseline: 1.0674x; 1.0674x over previous
#include <cuda_runtime.h>
#include <cstdint>

#define NF    16
#define NP    120
#define EMB   256
#define BATCH 2048

// ---- tcgen05 feature gate: only valid when the compile pass targets sm_103a/f ----
#if defined(__CUDA_ARCH__)
#  if (__CUDA_ARCH__ == 1030) && (defined(__CUDA_ARCH_FEAT_SM103_ALL) || \
       defined(__CUDA_ARCH_SPECIFIC__) || defined(__CUDA_ARCH_FAMILY_SPECIFIC__))
#    define USE_TCGEN 1
#  else
#    define USE_TCGEN 0
#  endif
#else
#  define USE_TCGEN 0
#endif

// ---- shared constants ----
#define BM 128
#define BN 256                    // full EMB per CTA
#define BK 32
#define NSTAGE 2
#define NITER  (EMB / BK)                 // 8 k-slabs
#define A_BYTES (BM * BK * 4)             // 16384
#define B_BYTES (BN * BK * 4)             // 32768
#define STAGE_BYTES (A_BYTES + B_BYTES)   // 49152
#define MBAR_OFF 16
#define STAGE0_OFF 1024
#define SMEM_NEEDED (STAGE0_OFF + NSTAGE * STAGE_BYTES)   // 99328
#define SMEM_ALLOC  (SMEM_NEEDED + 1024)                  // 100352 -> 2 CTAs/SM

#define TMEM_COLS 256
// idesc: dtype=F32(1)<<4, atype=TF32(2)<<7, btype=TF32(2)<<10, N/8<<17, M/16<<24
#define IDESC ((1u << 4) | (2u << 7) | (2u << 10) | ((BN / 8) << 17) | ((BM / 16) << 24))

__device__ float g_Wt[(size_t)NP * EMB * EMB];   // W^T scratch, [p][n][k], tf32-rounded

__device__ __forceinline__ float round_tf32(float v) {
    uint32_t u;
    asm("cvt.rna.tf32.f32 %0, %1;" : "=r"(u) : "f"(v));
    return __uint_as_float(u);
}

// ---------------- transpose W[p][k][n] -> g_Wt[p][n][k] ----------------
__global__ void transpose_w(const float* __restrict__ W) {
    __shared__ float t[32][33];
    const int p  = blockIdx.z;
    const int kb = blockIdx.x * 32;
    const int nb = blockIdx.y * 32;
    const float* Wp = W + (size_t)p * EMB * EMB;
    float* Wtp = g_Wt + (size_t)p * EMB * EMB;
    const int tx = threadIdx.x;
#pragma unroll
    for (int i = threadIdx.y; i < 32; i += 8)
        t[i][tx] = round_tf32(Wp[(size_t)(kb + i) * EMB + nb + tx]);
    __syncthreads();
#pragma unroll
    for (int i = threadIdx.y; i < 32; i += 8)
        Wtp[(size_t)(nb + i) * EMB + kb + tx] = t[tx][i];
}

#if USE_TCGEN
// ---------------- tcgen05 helpers ----------------
__device__ __forceinline__ uint32_t smem_u32(const void* p) {
    uint32_t a;
    asm("{ .reg .u64 t; cvta.to.shared.u64 t, %1; cvt.u32.u64 %0, t; }" : "=r"(a) : "l"(p));
    return a;
}
__device__ __forceinline__ uint32_t elect_one() {
    uint32_t pred;
    asm volatile("{ .reg .pred p; elect.sync _|p, 0xFFFFFFFF; selp.b32 %0, 1, 0, p; }" : "=r"(pred));
    return pred;
}
static __device__ __forceinline__ uint64_t make_desc(uint32_t addr) {
    // SW128 K-major: layout=2, version=1, SBO=64 (1024B), LBO=1 (16B)
    return ((uint64_t)2 << 61) | ((uint64_t)1 << 46) | ((uint64_t)64 << 32) |
           ((uint64_t)1 << 16) | (((uint64_t)addr >> 4) & 0x3FFF);
}
#define MBAR_INIT(a, n) asm volatile("mbarrier.init.shared.b64 [%0], %1;" :: "r"(a), "r"(n) : "memory")
__device__ __forceinline__ void mbar_wait(uint32_t mbar, uint32_t parity) {
    uint32_t done;
    asm volatile(
        "{ .reg .pred p; mbarrier.try_wait.parity.acquire.cta.shared::cta.b64 p, [%1], %2; selp.b32 %0, 1, 0, p; }"
        : "=r"(done) : "r"(mbar), "r"(parity) : "memory");
    if (!done) {
        asm volatile(
            "{ .reg .pred P1;\n"
            "W_%=: mbarrier.try_wait.parity.acquire.cta.shared::cta.b64 P1, [%0], %1, 0x989680;\n"
            "@P1 bra.uni D_%=; bra.uni W_%=;\nD_%=: }"
            :: "r"(mbar), "r"(parity) : "memory");
    }
}
__device__ __forceinline__ void cp16(uint32_t dst, const void* src) {
    asm volatile("cp.async.cg.shared.global [%0], [%1], 16;" :: "r"(dst), "l"(src));
}
#define CP_COMMIT() asm volatile("cp.async.commit_group;" ::: "memory")
#define CP_WAIT1()  asm volatile("cp.async.wait_group 1;" ::: "memory")
__device__ __forceinline__ void mma_tf32_ss(uint32_t d, uint64_t a, uint64_t b,
                                            uint32_t idesc, uint32_t en) {
    asm volatile(
        "{ .reg .pred p; setp.ne.u32 p, %4, 0;\n"
        "tcgen05.mma.cta_group::1.kind::tf32 [%0], %1, %2, %3, {%5,%5,%5,%5}, p; }"
        :: "r"(d), "l"(a), "l"(b), "r"(idesc), "r"(en), "r"(0u) : "memory");
}
#define TC_COMMIT(mbar) \
    asm volatile("tcgen05.commit.cta_group::1.mbarrier::arrive::one.shared::cluster.b64 [%0];" \
                 :: "r"(mbar) : "memory")
#define FENCE_ASYNC()     asm volatile("fence.proxy.async.shared::cta;" ::: "memory")
#define TC_FENCE_AFTER()  asm volatile("tcgen05.fence::after_thread_sync;" ::: "memory")
#define TC_FENCE_BEFORE() asm volatile("tcgen05.fence::before_thread_sync;" ::: "memory")
#define LDTM_X32(r, addr) \
    asm volatile("tcgen05.ld.sync.aligned.32x32b.x32.b32 " \
        "{%0,%1,%2,%3,%4,%5,%6,%7,%8,%9,%10,%11,%12,%13,%14,%15," \
        "%16,%17,%18,%19,%20,%21,%22,%23,%24,%25,%26,%27,%28,%29,%30,%31}, [%32];" \
        : "=r"((r)[0]),"=r"((r)[1]),"=r"((r)[2]),"=r"((r)[3]),"=r"((r)[4]),"=r"((r)[5]),"=r"((r)[6]),"=r"((r)[7]), \
          "=r"((r)[8]),"=r"((r)[9]),"=r"((r)[10]),"=r"((r)[11]),"=r"((r)[12]),"=r"((r)[13]),"=r"((r)[14]),"=r"((r)[15]), \
          "=r"((r)[16]),"=r"((r)[17]),"=r"((r)[18]),"=r"((r)[19]),"=r"((r)[20]),"=r"((r)[21]),"=r"((r)[22]),"=r"((r)[23]), \
          "=r"((r)[24]),"=r"((r)[25]),"=r"((r)[26]),"=r"((r)[27]),"=r"((r)[28]),"=r"((r)[29]),"=r"((r)[30]),"=r"((r)[31]) \
        : "r"(addr))
#define TC_WAIT_LD() asm volatile("tcgen05.wait::ld.sync.aligned;" ::: "memory")

__device__ __forceinline__ uint32_t swz(uint32_t off) { return off ^ ((off >> 3) & 0x70); }
#endif  // USE_TCGEN

#if !USE_TCGEN
// legacy mma.sync helpers (fallback cubin; not selected on GB300)
__device__ __forceinline__ uint32_t f2tf32(float v) {
    uint32_t u;
    asm("cvt.rna.tf32.f32 %0, %1;" : "=r"(u) : "f"(v));
    return u;
}
__device__ __forceinline__ void mma_tf32_16x8x8(float* d, const uint32_t* a, const uint32_t* b) {
    asm volatile(
        "mma.sync.aligned.m16n8k8.row.col.f32.tf32.tf32.f32 "
        "{%0,%1,%2,%3}, {%4,%5,%6,%7}, {%8,%9}, {%0,%1,%2,%3};"
        : "+f"(d[0]), "+f"(d[1]), "+f"(d[2]), "+f"(d[3])
        : "r"(a[0]), "r"(a[1]), "r"(a[2]), "r"(a[3]), "r"(b[0]), "r"(b[1]));
}
#endif

// ================= fused bilinear kernel: one symbol, two arch paths =================
// grid(16, 120), block 256, dynamic smem SMEM_ALLOC
__global__ __launch_bounds__(256, 2)
void bilinear_fused(const float* __restrict__ emb,
                    const float* __restrict__ weight,
                    const float* __restrict__ bias,
                    float* __restrict__ out) {
    const int tid = threadIdx.x;
    const int p   = blockIdx.y;
    // pair p -> (r_idx, c_idx) of triu_indices(16, 1)
    int r_idx = 0, rem = p;
    while (rem >= NF - 1 - r_idx) { rem -= NF - 1 - r_idx; r_idx++; }
    const int c_idx = r_idx + 1 + rem;
    const int m0 = blockIdx.x * BM;

#if USE_TCGEN
    // -------------------------------------------------- tcgen05 tf32 SS pipeline
    extern __shared__ char smem_raw[];
    const uint32_t base = (smem_u32(smem_raw) + 1023u) & ~1023u;
    const int wid  = tid >> 5;
    const int lane = tid & 31;

    if (wid == 0) {
        asm volatile("tcgen05.alloc.cta_group::1.sync.aligned.shared::cta.b32 [%0], %1;"
                     :: "r"(base), "r"((uint32_t)TMEM_COLS) : "memory");
        // CRITICAL: release the per-SM alloc permit NOW, or the co-resident CTA's
        // alloc stalls until this CTA exits (serializes the 2 CTAs -> R6 regression).
        asm volatile("tcgen05.relinquish_alloc_permit.cta_group::1.sync.aligned;");
    }
    if (tid == 0) {
#pragma unroll
        for (int s = 0; s < NSTAGE; s++) MBAR_INIT(base + MBAR_OFF + s * 8, 1);
    }
    __syncthreads();
    uint32_t tmem;
    asm volatile("ld.shared.b32 %0, [%1];" : "=r"(tmem) : "r"(base));

    const float* Wtp = g_Wt + (size_t)p * EMB * EMB;

    auto load_stage = [&](int s, int k0) {
        const uint32_t st = base + STAGE0_OFF + s * STAGE_BYTES;
#pragma unroll
        for (int i = 0; i < 4; i++) {                    // A: 128 rows x 8 chunks
            int idx = tid + i * 256;
            int m = idx >> 3, c = idx & 7;
            cp16(st + swz((m << 7) | (c << 4)),
                 emb + ((size_t)(m0 + m) * NF + r_idx) * EMB + k0 + c * 4);
        }
#pragma unroll
        for (int i = 0; i < 8; i++) {                    // B: 256 n-rows x 8 chunks
            int idx = tid + i * 256;
            int n = idx >> 3, c = idx & 7;
            cp16(st + A_BYTES + swz((n << 7) | (c << 4)),
                 Wtp + (size_t)n * EMB + k0 + c * 4);
        }
    };

    // prologue: stage 0
    load_stage(0, 0);
    CP_COMMIT();

    for (int it = 0; it < NITER; it++) {
        const int s = it & (NSTAGE - 1);
        const int j = it + 1;                      // next stage to load
        if (j < NITER) {
            const int s2 = j & (NSTAGE - 1);
            if (j >= NSTAGE)                       // slot reuse: wait prior occupant's MMA
                mbar_wait(base + MBAR_OFF + s2 * 8, ((j - NSTAGE) >> 1) & 1);
            load_stage(s2, j * BK);
        }
        CP_COMMIT();                               // uniform group count
        CP_WAIT1();                                // stage `it` resident
        FENCE_ASYNC();
        __syncthreads();

        if (wid == 0 && elect_one()) {
            const uint32_t st = base + STAGE0_OFF + s * STAGE_BYTES;
            const uint64_t ad = make_desc(st);
            const uint64_t bd = make_desc(st + A_BYTES);
#pragma unroll
            for (int jj = 0; jj < 4; jj++)         // 4 x (K=8) per 32-float slab
                mma_tf32_ss(tmem, ad + jj * 2, bd + jj * 2, IDESC,
                            (it == 0 && jj == 0) ? 0u : 1u);
            TC_COMMIT(base + MBAR_OFF + s * 8);
        }
    }

    // final MMA completion: slot (NITER-1)&1 = 1; 4th arrival -> phase 3 -> parity 1
    mbar_wait(base + MBAR_OFF + ((NITER - 1) & (NSTAGE - 1)) * 8, 1);
    TC_FENCE_AFTER();

    // epilogue: warps 0-3 -> cols [0,128), warps 4-7 -> cols [128,256)
    // row = (wid&3)*32 + lane (warp reads its own TMEM subpartition)
    {
        const int sub  = wid & 3;
        const int half = wid >> 2;
        const int m = m0 + sub * 32 + lane;
        const float* qrow = emb + ((size_t)m * NF + c_idx) * EMB;
        const float* brow = bias + (size_t)p * EMB;
        float* orow = out + ((size_t)m * NP + p) * EMB;
#pragma unroll
        for (int c = 0; c < 4; c++) {
            const int col = half * 128 + c * 32;
            uint32_t r[32];
            LDTM_X32(r, tmem + col);
            TC_WAIT_LD();
#pragma unroll
            for (int jj = 0; jj < 8; jj++) {
                const int gn = col + jj * 4;
                const float4 q  = *(const float4*)(qrow + gn);
                const float4 bb = *(const float4*)(brow + gn);
                float4 o;
                o.x = __uint_as_float(r[jj * 4 + 0]) * q.x + bb.x;
                o.y = __uint_as_float(r[jj * 4 + 1]) * q.y + bb.y;
                o.z = __uint_as_float(r[jj * 4 + 2]) * q.z + bb.z;
                o.w = __uint_as_float(r[jj * 4 + 3]) * q.w + bb.w;
                *(float4*)(orow + gn) = o;
            }
        }
    }
    TC_FENCE_BEFORE();
    __syncthreads();
    if (wid == 0) {
        asm volatile("tcgen05.dealloc.cta_group::1.sync.aligned.b32 %0, %1;"
                     :: "r"(tmem), "r"((uint32_t)TMEM_COLS));
    }

#else
    // -------------------------------------------------- legacy mma.sync tf32 fallback
    // covers the 128x256 CTA tile as two 128x128 passes
    __shared__ uint32_t As[BK * 132];
    __shared__ uint32_t Bs[BK * 132];
    const int lane = tid & 31;
    const int warp = tid >> 5;
    const int warp_m = warp & 3;
    const int warp_n = warp >> 2;
    const float* Wp = weight + (size_t)p * EMB * EMB;
    const int lr = lane >> 2;
    const int lc = lane & 3;

    for (int nb = 0; nb < 2; nb++) {
        const int n0 = nb * 128;
        float acc[2][8][4];
#pragma unroll
        for (int i = 0; i < 2; i++)
#pragma unroll
            for (int j = 0; j < 8; j++)
#pragma unroll
                for (int r = 0; r < 4; r++) acc[i][j][r] = 0.0f;

        for (int k0 = 0; k0 < EMB; k0 += BK) {
            __syncthreads();
#pragma unroll
            for (int it = 0; it < 4; it++) {
                int fid = tid + it * 256;
                int m   = fid >> 3;
                int k4  = fid & 7;
                const float4 v = *(const float4*)(emb + ((size_t)(m0 + m) * NF + r_idx) * EMB + k0 + k4 * 4);
                As[(k4 * 4 + 0) * 132 + m] = f2tf32(v.x);
                As[(k4 * 4 + 1) * 132 + m] = f2tf32(v.y);
                As[(k4 * 4 + 2) * 132 + m] = f2tf32(v.z);
                As[(k4 * 4 + 3) * 132 + m] = f2tf32(v.w);
            }
#pragma unroll
            for (int it = 0; it < 4; it++) {
                int fid = tid + it * 256;
                int k   = fid >> 5;
                int n4  = fid & 31;
                const float4 w = *(const float4*)(Wp + (size_t)(k0 + k) * EMB + n0 + n4 * 4);
                Bs[k * 132 + n4 * 4 + 0] = f2tf32(w.x);
                Bs[k * 132 + n4 * 4 + 1] = f2tf32(w.y);
                Bs[k * 132 + n4 * 4 + 2] = f2tf32(w.z);
                Bs[k * 132 + n4 * 4 + 3] = f2tf32(w.w);
            }
            __syncthreads();

#pragma unroll
            for (int kk = 0; kk < BK; kk += 8) {
                uint32_t a[2][4];
                uint32_t b[8][2];
#pragma unroll
                for (int i = 0; i < 2; i++) {
                    int mbase = warp_m * 32 + i * 16 + lr;
                    a[i][0] = As[(kk + lc) * 132 + mbase];
                    a[i][1] = As[(kk + lc) * 132 + mbase + 8];
                    a[i][2] = As[(kk + lc + 4) * 132 + mbase];
                    a[i][3] = As[(kk + lc + 4) * 132 + mbase + 8];
                }
#pragma unroll
                for (int j = 0; j < 8; j++) {
                    int nbase = warp_n * 64 + j * 8 + lr;
                    b[j][0] = Bs[(kk + lc) * 132 + nbase];
                    b[j][1] = Bs[(kk + lc + 4) * 132 + nbase];
                }
#pragma unroll
                for (int i = 0; i < 2; i++)
#pragma unroll
                    for (int j = 0; j < 8; j++)
                        mma_tf32_16x8x8(acc[i][j], a[i], b[j]);
            }
        }

#pragma unroll
        for (int i = 0; i < 2; i++) {
            const int gm0 = m0 + warp_m * 32 + i * 16 + lr;
#pragma unroll
            for (int j = 0; j < 8; j++) {
                const int gn = n0 + warp_n * 64 + j * 8 + lc * 2;
                const float2 bs = *(const float2*)(bias + (size_t)p * EMB + gn);

                const float2 q0 = *(const float2*)(emb + ((size_t)gm0 * NF + c_idx) * EMB + gn);
                float2 o0;
                o0.x = acc[i][j][0] * q0.x + bs.x;
                o0.y = acc[i][j][1] * q0.y + bs.y;
                *(float2*)(out + ((size_t)gm0 * NP + p) * EMB + gn) = o0;

                const float2 q1 = *(const float2*)(emb + ((size_t)(gm0 + 8) * NF + c_idx) * EMB + gn);
                float2 o1;
                o1.x = acc[i][j][2] * q1.x + bs.x;
                o1.y = acc[i][j][3] * q1.y + bs.y;
                *(float2*)(out + ((size_t)(gm0 + 8) * NP + p) * EMB + gn) = o1;
            }
        }
        __syncthreads();
    }
#endif
}

extern "C" void kernel_launch(void* const* d_in, const int* in_sizes, int n_in,
                              void* d_out, int out_size) {
    const float* emb    = (const float*)d_in[0];
    const float* weight = (const float*)d_in[1];
    const float* bias   = (const float*)d_in[2];
    float* out          = (float*)d_out;

    cudaFuncSetAttribute(bilinear_fused, cudaFuncAttributeMaxDynamicSharedMemorySize, SMEM_ALLOC);

    transpose_w<<<dim3(8, 8, NP), dim3(32, 8)>>>(weight);
    bilinear_fused<<<dim3(BATCH / BM, NP), 256, SMEM_ALLOC>>>(emb, weight, bias, out);
}